// round 11
// baseline (speedup 1.0000x reference)
#include <cuda_runtime.h>
#include <cstdint>
#include <cmath>

#define B_ 128
#define T_ 512
#define I_ 256
#define H_ 512
#define NCTA 128
#define GRP 64          // CTAs per barrier group (one per b-slice)

// ---- static device scratch ----
__device__ float  g_xproj[(size_t)4 * T_ * B_ * H_];   // [g][t][b][h]
__device__ float  g_hn[2][H_][B_];                     // hidden state, h-major, NOT duplicated
__device__ unsigned g_cnt[2][32];                      // per-group barrier counter (padded)
__device__ unsigned g_sns[2][32];                      // per-group barrier sense (persists)

// ---- packed fp32x2 ops ----
__device__ __forceinline__ void fma2(unsigned long long& d,
                                     unsigned long long a,
                                     unsigned long long b) {
    asm("fma.rn.f32x2 %0, %1, %2, %0;" : "+l"(d) : "l"(a), "l"(b));
}
__device__ __forceinline__ void add2(unsigned long long& d, unsigned long long a) {
    asm("add.rn.f32x2 %0, %0, %1;" : "+l"(d) : "l"(a));
}
__device__ __forceinline__ float lo32(unsigned long long v) {
    return __uint_as_float((unsigned)(v & 0xffffffffull));
}
__device__ __forceinline__ float hi32(unsigned long long v) {
    return __uint_as_float((unsigned)(v >> 32));
}
__device__ __forceinline__ float rcpa(float x) {
    float r;
    asm("rcp.approx.f32 %0, %1;" : "=f"(r) : "f"(x));
    return r;
}
// rational tanh numerator/denominator (Eigen coefficients)
__device__ __forceinline__ void tanh_pq(float x, float& p, float& q) {
    x = fminf(fmaxf(x, -7.90531110763549805f), 7.90531110763549805f);
    float x2 = x * x;
    float pp = fmaf(x2, -2.76076847742355e-16f, 2.00018790482477e-13f);
    pp = fmaf(pp, x2, -8.60467152213735e-11f);
    pp = fmaf(pp, x2, 5.12229709037114e-08f);
    pp = fmaf(pp, x2, 1.48572235717979e-05f);
    pp = fmaf(pp, x2, 6.37261928875436e-04f);
    pp = fmaf(pp, x2, 4.89352455891786e-03f);
    p = pp * x;
    float qq = fmaf(x2, 1.19825839466702e-06f, 1.18534705686654e-04f);
    qq = fmaf(qq, x2, 2.26843463243900e-03f);
    q = fmaf(qq, x2, 4.89352518554385e-03f);
}
__device__ __forceinline__ void div4(const float* p, const float* q, float* o) {
    float q01 = q[0] * q[1], q23 = q[2] * q[3];
    float r   = rcpa(q01 * q23);
    float r01 = q23 * r, r23 = q01 * r;
    o[0] = p[0] * (q[1] * r01);
    o[1] = p[1] * (q[0] * r01);
    o[2] = p[2] * (q[3] * r23);
    o[3] = p[3] * (q[2] * r23);
}
__device__ __forceinline__ void teambar(int team) {
    asm volatile("bar.sync %0, %1;" :: "r"(team + 1), "r"(128) : "memory");
}

// ---------------------------------------------------------------------------
// projection GEMM (unchanged, proven): g_xproj[g][t][b][h] = x.W_g^T + b_g
// ---------------------------------------------------------------------------
__global__ __launch_bounds__(128) void lstm_proj(
    const float* __restrict__ x,
    const float* __restrict__ Wz, const float* __restrict__ Ws,
    const float* __restrict__ Wf, const float* __restrict__ Wo,
    const float* __restrict__ bz, const float* __restrict__ bs,
    const float* __restrict__ bf, const float* __restrict__ bo)
{
    __shared__ __align__(16) float2 As2[32][64];
    __shared__ __align__(16) float  Bs[32][64];

    const int tid = threadIdx.x;
    const int r0  = blockIdx.x * 64;
    const int n0  = blockIdx.y * 64;
    const int g   = n0 >> 9;
    const int h0  = n0 & 511;

    const float* W    = (g == 0) ? Wz : (g == 1) ? Ws : (g == 2) ? Wf : Wo;
    const float* bias = (g == 0) ? bz : (g == 1) ? bs : (g == 2) ? bf : bo;

    const int tn = tid & 7;
    const int tm = tid >> 3;
    const int lm = tid & 63;
    const int qb = (tid >> 6) * 4;
    const float* xr = x + (size_t)(r0 + lm) * I_;
    const float* wr = W + (size_t)(h0 + lm) * I_;

    unsigned long long acc[4][4];
#pragma unroll
    for (int i = 0; i < 4; i++)
#pragma unroll
        for (int j = 0; j < 4; j++) acc[i][j] = 0ull;

    float4 pa[4], pw[4];
#pragma unroll
    for (int i = 0; i < 4; i++) {
        pa[i] = *(const float4*)(xr + (qb + i) * 4);
        pw[i] = *(const float4*)(wr + (qb + i) * 4);
    }

    for (int kt = 0; kt < I_ / 32; kt++) {
#pragma unroll
        for (int i = 0; i < 4; i++) {
            int q = qb + i;
            As2[q * 4 + 0][lm] = make_float2(pa[i].x, pa[i].x);
            As2[q * 4 + 1][lm] = make_float2(pa[i].y, pa[i].y);
            As2[q * 4 + 2][lm] = make_float2(pa[i].z, pa[i].z);
            As2[q * 4 + 3][lm] = make_float2(pa[i].w, pa[i].w);
            Bs[q * 4 + 0][lm] = pw[i].x;
            Bs[q * 4 + 1][lm] = pw[i].y;
            Bs[q * 4 + 2][lm] = pw[i].z;
            Bs[q * 4 + 3][lm] = pw[i].w;
        }
        __syncthreads();
        if (kt + 1 < I_ / 32) {
            int k0 = (kt + 1) * 32;
#pragma unroll
            for (int i = 0; i < 4; i++) {
                pa[i] = *(const float4*)(xr + k0 + (qb + i) * 4);
                pw[i] = *(const float4*)(wr + k0 + (qb + i) * 4);
            }
        }
#pragma unroll
        for (int kk = 0; kk < 32; kk++) {
            ulonglong2 a01 = *(const ulonglong2*)&As2[kk][tm * 4];
            ulonglong2 a23 = *(const ulonglong2*)&As2[kk][tm * 4 + 2];
            ulonglong2 b01 = *(const ulonglong2*)&Bs[kk][tn * 8];
            ulonglong2 b23 = *(const ulonglong2*)&Bs[kk][tn * 8 + 4];
            fma2(acc[0][0], a01.x, b01.x); fma2(acc[0][1], a01.x, b01.y);
            fma2(acc[0][2], a01.x, b23.x); fma2(acc[0][3], a01.x, b23.y);
            fma2(acc[1][0], a01.y, b01.x); fma2(acc[1][1], a01.y, b01.y);
            fma2(acc[1][2], a01.y, b23.x); fma2(acc[1][3], a01.y, b23.y);
            fma2(acc[2][0], a23.x, b01.x); fma2(acc[2][1], a23.x, b01.y);
            fma2(acc[2][2], a23.x, b23.x); fma2(acc[2][3], a23.x, b23.y);
            fma2(acc[3][0], a23.y, b01.x); fma2(acc[3][1], a23.y, b01.y);
            fma2(acc[3][2], a23.y, b23.x); fma2(acc[3][3], a23.y, b23.y);
        }
        __syncthreads();
    }

    float bv[8];
#pragma unroll
    for (int j = 0; j < 8; j++) bv[j] = bias[h0 + tn * 8 + j];
#pragma unroll
    for (int i = 0; i < 4; i++) {
        int r  = r0 + tm * 4 + i;
        int bb = r >> 9;
        int tt = r & 511;
        float* orow = g_xproj + (((size_t)g * T_ + tt) * B_ + bb) * H_ + h0 + tn * 8;
#pragma unroll
        for (int jp = 0; jp < 4; jp++) {
            float2 v = make_float2(lo32(acc[i][jp]) + bv[jp * 2],
                                   hi32(acc[i][jp]) + bv[jp * 2 + 1]);
            *(float2*)(orow + jp * 2) = v;
        }
    }
}

// ---------------------------------------------------------------------------
// persistent recurrence: 128 CTAs x 256 threads, 2 k-teams of 128.
// CTA tile: M=32 (4g x 8h) x N=64 batch x K=512 (K split 256/team).
// Micro: 4m x 4n per thread (8 FFMA2 per 3 LDS.128).
// smem: Rsm[512][32] 64KB | Hdup[2][64][64]f2 64KB | act[32][66] | red[256][4]ull
// ---------------------------------------------------------------------------
__global__ __launch_bounds__(256, 1) void lstm_recur(
    const float* __restrict__ Rz, const float* __restrict__ Rs_,
    const float* __restrict__ Rf, const float* __restrict__ Ro,
    float* __restrict__ out)
{
    extern __shared__ float sm[];
    float*  Rsm  = sm;                                     // [512][32]
    float2* Hdup = (float2*)(sm + 512 * 32);               // [2][64][64]
    float*  act  = sm + 512 * 32 + 2 * 64 * 64 * 2;        // [32][66]
    unsigned long long* red =
        (unsigned long long*)(act + 32 * 66 + 2);          // [256][4]

    const int tid  = threadIdx.x;
    const int cta  = blockIdx.x;
    const int bg   = cta & 1;
    const int b0   = bg * 64;
    const int h0   = (cta >> 1) * 8;

    const int team = tid >> 7;
    const int ltid = tid & 127;
    const int mg   = ltid & 7;          // m0 = mg*4
    const int ng   = ltid >> 3;         // n0 = ng*4
    const int m0   = mg * 4;
    const int n0   = ng * 4;
    const int gt   = mg >> 1;           // gate (uniform per warp)
    const int hrb  = (mg & 1) * 4;      // h-row base (4 rows)
    const int kb   = team * 256;        // this team's K range

    unsigned s0 = 0;
    if (tid == 0) s0 = *(volatile unsigned*)&g_sns[bg][0];

    // ---- load R tile once: Rsm[k][m], m = gate*8 + hrow ----
    {
        int m  = tid & 31;
        int kq = (tid >> 5) * 64;
        int rg = m >> 3, hh = m & 7;
        const float* Rp = ((rg == 0) ? Rz : (rg == 1) ? Rs_ : (rg == 2) ? Rf : Ro)
                        + (size_t)(h0 + hh) * H_ + kq;
#pragma unroll 4
        for (int j = 0; j < 64; j += 4) {
            float4 v = *(const float4*)(Rp + j);
            Rsm[(kq + j + 0) * 32 + m] = v.x;
            Rsm[(kq + j + 1) * 32 + m] = v.y;
            Rsm[(kq + j + 2) * 32 + m] = v.z;
            Rsm[(kq + j + 3) * 32 + m] = v.w;
        }
    }
    __syncthreads();

    // combine identity: 2 cells (b0+bb, h0+hh), (b0+bb+1, h0+hh)
    const int hh = (tid * 2) >> 6;      // 0..7
    const int bb = (tid * 2) & 63;      // even
    float creg0 = 0.0f, creg1 = 0.0f;
    float hsum0 = 0.0f, hsum1 = 0.0f;

    // staging role: thread covers 32 floats of one k-row
    const int krow = ltid >> 1;
    const int cs   = (ltid & 1) * 32;

    for (int t = 0; t < T_; t++) {
        // prefetch xproj for this thread's 8 final cells (2 n after exchange)
        float4 xq[2];
        {
            const int nA = n0 + team * 2;
            const float* xb = g_xproj + (((size_t)gt * T_ + t) * B_ + b0 + nA) * H_
                            + h0 + hrb;
            xq[0] = *(const float4*)xb;
            xq[1] = *(const float4*)(xb + H_);
        }

        unsigned long long acc[2][4];
#pragma unroll
        for (int i = 0; i < 2; i++)
#pragma unroll
            for (int j = 0; j < 4; j++) acc[i][j] = 0ull;

        if (t > 0) {
            const float* hbase = &g_hn[t & 1][0][0];
            float4 pf[8];
            {   // prefetch chunk 0
                const float* hs = hbase + (size_t)(kb + krow) * B_ + b0 + cs;
#pragma unroll
                for (int i = 0; i < 8; i++) pf[i] = *(const float4*)(hs + i * 4);
            }
            for (int c = 0; c < 4; c++) {
                teambar(team);              // Hdup[team] free
                {   // dup-expand into smem
                    float2* drow = Hdup + (size_t)team * 4096 + krow * 64;
#pragma unroll
                    for (int i = 0; i < 8; i++) {
                        float4 v = pf[i];
                        int col = cs + i * 4;
                        *(float4*)&drow[col]     = make_float4(v.x, v.x, v.y, v.y);
                        *(float4*)&drow[col + 2] = make_float4(v.z, v.z, v.w, v.w);
                    }
                }
                teambar(team);
                if (c < 3) {                // prefetch next chunk (hidden by GEMM)
                    const float* hs = hbase + (size_t)(kb + (c + 1) * 64 + krow) * B_
                                    + b0 + cs;
#pragma unroll
                    for (int i = 0; i < 8; i++) pf[i] = *(const float4*)(hs + i * 4);
                }
                const float*  Rk = Rsm + (kb + c * 64) * 32 + m0;
                const float2* Hk = Hdup + (size_t)team * 4096 + n0;
#pragma unroll 8
                for (int kk = 0; kk < 64; kk++) {
                    ulonglong2 rv  = *(const ulonglong2*)(Rk + kk * 32);
                    ulonglong2 h01 = *(const ulonglong2*)(Hk + kk * 64);
                    ulonglong2 h23 = *(const ulonglong2*)(Hk + kk * 64 + 2);
                    fma2(acc[0][0], rv.x, h01.x); fma2(acc[0][1], rv.x, h01.y);
                    fma2(acc[0][2], rv.x, h23.x); fma2(acc[0][3], rv.x, h23.y);
                    fma2(acc[1][0], rv.y, h01.x); fma2(acc[1][1], rv.y, h01.y);
                    fma2(acc[1][2], rv.y, h23.x); fma2(acc[1][3], rv.y, h23.y);
                }
            }
        }

        // ---- cross-team reduction: exchange the n-half we don't keep ----
        {
            int snb = (1 - team) * 2;       // nj pair this thread sends
#pragma unroll
            for (int mp = 0; mp < 2; mp++) {
                red[tid * 4 + mp * 2 + 0] = acc[mp][snb + 0];
                red[tid * 4 + mp * 2 + 1] = acc[mp][snb + 1];
            }
        }
        __syncthreads();
        {
            int knb = team * 2;             // nj pair this thread keeps
            int ptn = tid ^ 128;
#pragma unroll
            for (int mp = 0; mp < 2; mp++) {
                add2(acc[mp][knb + 0], red[ptn * 4 + mp * 2 + 0]);
                add2(acc[mp][knb + 1], red[ptn * 4 + mp * 2 + 1]);
            }
        }

        // ---- epilogue: 8 pre-activations -> rational tanh/sigmoid ----
        {
            const int knb = team * 2;
            float pre[8];
#pragma unroll
            for (int nl = 0; nl < 2; nl++) {
                float4 xp = xq[nl];
                pre[nl * 2 + 0] = lo32(acc[0][knb + nl]) + xp.x;   // h=hrb
                pre[nl * 2 + 1] = hi32(acc[0][knb + nl]) + xp.y;   // h=hrb+1
                pre[nl * 2 + 4] = lo32(acc[1][knb + nl]) + xp.z;   // h=hrb+2
                pre[nl * 2 + 5] = hi32(acc[1][knb + nl]) + xp.w;   // h=hrb+3
            }
            const bool  isz = (gt == 0);
            const float s1  = isz ? 1.0f : 0.5f;
            const float scm = isz ? 1.0f : 0.5f;
            const float sca = isz ? 0.0f : 0.5f;

            float pn[8], qn[8], av[8];
#pragma unroll
            for (int i = 0; i < 8; i++) tanh_pq(pre[i] * s1, pn[i], qn[i]);
            div4(pn, qn, av);
            div4(pn + 4, qn + 4, av + 4);
#pragma unroll
            for (int i = 0; i < 8; i++) av[i] = fmaf(av[i], scm, sca);

            // store: act[(hr*4+g)*66 + n]
#pragma unroll
            for (int mp = 0; mp < 2; mp++)
#pragma unroll
                for (int nl = 0; nl < 2; nl++) {
                    int n = n0 + knb + nl;
                    act[((hrb + mp * 2 + 0) * 4 + gt) * 66 + n] = av[mp * 4 + nl * 2 + 0];
                    act[((hrb + mp * 2 + 1) * 4 + gt) * 66 + n] = av[mp * 4 + nl * 2 + 1];
                }
        }
        __syncthreads();

        // ---- combine: 2 cells; c,h update; h store (non-dup); h-sum ----
        {
            float2 zv = *(const float2*)&act[(hh * 4 + 0) * 66 + bb];
            float2 sv = *(const float2*)&act[(hh * 4 + 1) * 66 + bb];
            float2 fv = *(const float2*)&act[(hh * 4 + 2) * 66 + bb];
            float2 ov = *(const float2*)&act[(hh * 4 + 3) * 66 + bb];
            float c0 = fmaf(sv.x, zv.x, fv.x * creg0);
            float c1 = fmaf(sv.y, zv.y, fv.y * creg1);
            creg0 = c0; creg1 = c1;
            float p0, q0, p1, q1;
            tanh_pq(c0, p0, q0);
            tanh_pq(c1, p1, q1);
            float r  = rcpa(q0 * q1);
            float hn0 = ov.x * (p0 * (q1 * r));
            float hn1 = ov.y * (p1 * (q0 * r));
            hsum0 += hn0; hsum1 += hn1;
            *(float2*)&g_hn[(t + 1) & 1][h0 + hh][b0 + bb] = make_float2(hn0, hn1);
        }

        if (t < T_ - 1) {
            __syncthreads();               // all h stores done before arrival
            if (tid == 0) {
                unsigned target = s0 + (unsigned)(t + 1);
                __threadfence();
                unsigned arr = atomicAdd(&g_cnt[bg][0], 1u);
                if (arr == GRP - 1) {
                    g_cnt[bg][0] = 0;
                    asm volatile("st.release.gpu.u32 [%0], %1;"
                                 :: "l"(&g_sns[bg][0]), "r"(target) : "memory");
                } else {
                    unsigned v;
                    do {
                        asm volatile("ld.acquire.gpu.u32 %0, [%1];"
                                     : "=r"(v) : "l"(&g_sns[bg][0]) : "memory");
                    } while ((int)(v - target) < 0);
                }
            }
            __syncthreads();
        } else {
            out[(size_t)(b0 + bb) * H_ + h0 + hh]     = hsum0 * (1.0f / (float)T_);
            out[(size_t)(b0 + bb + 1) * H_ + h0 + hh] = hsum1 * (1.0f / (float)T_);
        }
    }
}

// ---------------------------------------------------------------------------
extern "C" void kernel_launch(void* const* d_in, const int* in_sizes, int n_in,
                              void* d_out, int out_size) {
    const float* x  = (const float*)d_in[0];
    const float* Wz = (const float*)d_in[1];
    const float* Ws = (const float*)d_in[2];
    const float* Wf = (const float*)d_in[3];
    const float* Wo = (const float*)d_in[4];
    const float* Rz = (const float*)d_in[5];
    const float* Rs = (const float*)d_in[6];
    const float* Rf = (const float*)d_in[7];
    const float* Ro = (const float*)d_in[8];
    const float* bz = (const float*)d_in[9];
    const float* bs = (const float*)d_in[10];
    const float* bf = (const float*)d_in[11];
    const float* bo = (const float*)d_in[12];

    // Rsm 64KB + Hdup 64KB + act + red
    const int smem_bytes = (512 * 32 + 2 * 64 * 64 * 2 + 32 * 66 + 2) * 4
                         + 256 * 4 * 8;   // ~153KB
    cudaFuncSetAttribute(lstm_recur,
                         cudaFuncAttributeMaxDynamicSharedMemorySize, smem_bytes);

    lstm_proj<<<dim3((B_ * T_) / 64, (4 * H_) / 64), 128>>>(
        x, Wz, Ws, Wf, Wo, bz, bs, bf, bo);
    lstm_recur<<<NCTA, 256, smem_bytes>>>(Rz, Rs, Rf, Ro, (float*)d_out);
}

// round 13
// speedup vs baseline: 2.4322x; 2.4322x over previous
#include <cuda_runtime.h>
#include <cuda_fp16.h>
#include <cstdint>
#include <cmath>

#define B_ 128
#define T_ 512
#define I_ 256
#define H_ 512
#define RCTAS 128
#define GRPSZ 32          // CTAs per barrier group (one per b-slice)

// ---- static device scratch ----
__device__ float    g_xproj[(size_t)4 * T_ * B_ * H_];  // [g][t][b][h]
__device__ __half   g_hH[2][B_][H_];                    // h fp16 [buf][b][h]
__device__ unsigned g_cnt[4][32];                       // per-group barrier counter
__device__ unsigned g_sns[4][32];                       // per-group barrier sense (persists)

// ---- packed fp32x2 (projection kernel) ----
__device__ __forceinline__ void fma2(unsigned long long& d,
                                     unsigned long long a,
                                     unsigned long long b) {
    asm("fma.rn.f32x2 %0, %1, %2, %0;" : "+l"(d) : "l"(a), "l"(b));
}
__device__ __forceinline__ float lo32(unsigned long long v) {
    return __uint_as_float((unsigned)(v & 0xffffffffull));
}
__device__ __forceinline__ float hi32(unsigned long long v) {
    return __uint_as_float((unsigned)(v >> 32));
}
__device__ __forceinline__ float rcpa(float x) {
    float r;
    asm("rcp.approx.f32 %0, %1;" : "=f"(r) : "f"(x));
    return r;
}
// rational tanh p/q (Eigen coefficients, float-accurate)
__device__ __forceinline__ void tanh_pq(float x, float& p, float& q) {
    x = fminf(fmaxf(x, -7.90531110763549805f), 7.90531110763549805f);
    float x2 = x * x;
    float pp = fmaf(x2, -2.76076847742355e-16f, 2.00018790482477e-13f);
    pp = fmaf(pp, x2, -8.60467152213735e-11f);
    pp = fmaf(pp, x2, 5.12229709037114e-08f);
    pp = fmaf(pp, x2, 1.48572235717979e-05f);
    pp = fmaf(pp, x2, 6.37261928875436e-04f);
    pp = fmaf(pp, x2, 4.89352455891786e-03f);
    p = pp * x;
    float qq = fmaf(x2, 1.19825839466702e-06f, 1.18534705686654e-04f);
    qq = fmaf(qq, x2, 2.26843463243900e-03f);
    q = fmaf(qq, x2, 4.89352518554385e-03f);
}
__device__ __forceinline__ void div4(const float* p, const float* q, float* o) {
    float q01 = q[0] * q[1], q23 = q[2] * q[3];
    float r   = rcpa(q01 * q23);
    float r01 = q23 * r, r23 = q01 * r;
    o[0] = p[0] * (q[1] * r01);
    o[1] = p[1] * (q[0] * r01);
    o[2] = p[2] * (q[3] * r23);
    o[3] = p[3] * (q[2] * r23);
}

// ---- warp MMA helpers (sm_80+ paths; valid on plain sm_103 target) ----
__device__ __forceinline__ void ldsm4(uint32_t& r0, uint32_t& r1, uint32_t& r2,
                                      uint32_t& r3, uint32_t addr) {
    asm volatile("ldmatrix.sync.aligned.m8n8.x4.shared.b16 {%0,%1,%2,%3}, [%4];"
                 : "=r"(r0), "=r"(r1), "=r"(r2), "=r"(r3) : "r"(addr));
}
__device__ __forceinline__ void ldsm2(uint32_t& r0, uint32_t& r1, uint32_t addr) {
    asm volatile("ldmatrix.sync.aligned.m8n8.x2.shared.b16 {%0,%1}, [%2];"
                 : "=r"(r0), "=r"(r1) : "r"(addr));
}
__device__ __forceinline__ void mma16816(float* c, uint32_t a0, uint32_t a1,
                                         uint32_t a2, uint32_t a3,
                                         uint32_t b0, uint32_t b1) {
    asm volatile(
        "mma.sync.aligned.m16n8k16.row.col.f32.f16.f16.f32 "
        "{%0,%1,%2,%3}, {%4,%5,%6,%7}, {%8,%9}, {%0,%1,%2,%3};"
        : "+f"(c[0]), "+f"(c[1]), "+f"(c[2]), "+f"(c[3])
        : "r"(a0), "r"(a1), "r"(a2), "r"(a3), "r"(b0), "r"(b1));
}

// ---------------------------------------------------------------------------
// projection GEMM (proven R6-R10): g_xproj[g][t][b][h] = x.W_g^T + b_g
// ---------------------------------------------------------------------------
__global__ __launch_bounds__(128) void lstm_proj(
    const float* __restrict__ x,
    const float* __restrict__ Wz, const float* __restrict__ Ws,
    const float* __restrict__ Wf, const float* __restrict__ Wo,
    const float* __restrict__ bz, const float* __restrict__ bs,
    const float* __restrict__ bf, const float* __restrict__ bo)
{
    __shared__ __align__(16) float2 As2[32][64];
    __shared__ __align__(16) float  Bs[32][64];

    const int tid = threadIdx.x;
    const int r0  = blockIdx.x * 64;
    const int n0  = blockIdx.y * 64;
    const int g   = n0 >> 9;
    const int h0  = n0 & 511;

    const float* W    = (g == 0) ? Wz : (g == 1) ? Ws : (g == 2) ? Wf : Wo;
    const float* bias = (g == 0) ? bz : (g == 1) ? bs : (g == 2) ? bf : bo;

    const int tn = tid & 7;
    const int tm = tid >> 3;
    const int lm = tid & 63;
    const int qb = (tid >> 6) * 4;
    const float* xr = x + (size_t)(r0 + lm) * I_;
    const float* wr = W + (size_t)(h0 + lm) * I_;

    unsigned long long acc[4][4];
#pragma unroll
    for (int i = 0; i < 4; i++)
#pragma unroll
        for (int j = 0; j < 4; j++) acc[i][j] = 0ull;

    float4 pa[4], pw[4];
#pragma unroll
    for (int i = 0; i < 4; i++) {
        pa[i] = *(const float4*)(xr + (qb + i) * 4);
        pw[i] = *(const float4*)(wr + (qb + i) * 4);
    }

    for (int kt = 0; kt < I_ / 32; kt++) {
#pragma unroll
        for (int i = 0; i < 4; i++) {
            int q = qb + i;
            As2[q * 4 + 0][lm] = make_float2(pa[i].x, pa[i].x);
            As2[q * 4 + 1][lm] = make_float2(pa[i].y, pa[i].y);
            As2[q * 4 + 2][lm] = make_float2(pa[i].z, pa[i].z);
            As2[q * 4 + 3][lm] = make_float2(pa[i].w, pa[i].w);
            Bs[q * 4 + 0][lm] = pw[i].x;
            Bs[q * 4 + 1][lm] = pw[i].y;
            Bs[q * 4 + 2][lm] = pw[i].z;
            Bs[q * 4 + 3][lm] = pw[i].w;
        }
        __syncthreads();
        if (kt + 1 < I_ / 32) {
            int k0 = (kt + 1) * 32;
#pragma unroll
            for (int i = 0; i < 4; i++) {
                pa[i] = *(const float4*)(xr + k0 + (qb + i) * 4);
                pw[i] = *(const float4*)(wr + k0 + (qb + i) * 4);
            }
        }
#pragma unroll
        for (int kk = 0; kk < 32; kk++) {
            ulonglong2 a01 = *(const ulonglong2*)&As2[kk][tm * 4];
            ulonglong2 a23 = *(const ulonglong2*)&As2[kk][tm * 4 + 2];
            ulonglong2 b01 = *(const ulonglong2*)&Bs[kk][tn * 8];
            ulonglong2 b23 = *(const ulonglong2*)&Bs[kk][tn * 8 + 4];
            fma2(acc[0][0], a01.x, b01.x); fma2(acc[0][1], a01.x, b01.y);
            fma2(acc[0][2], a01.x, b23.x); fma2(acc[0][3], a01.x, b23.y);
            fma2(acc[1][0], a01.y, b01.x); fma2(acc[1][1], a01.y, b01.y);
            fma2(acc[1][2], a01.y, b23.x); fma2(acc[1][3], a01.y, b23.y);
            fma2(acc[2][0], a23.x, b01.x); fma2(acc[2][1], a23.x, b01.y);
            fma2(acc[2][2], a23.x, b23.x); fma2(acc[2][3], a23.x, b23.y);
            fma2(acc[3][0], a23.y, b01.x); fma2(acc[3][1], a23.y, b01.y);
            fma2(acc[3][2], a23.y, b23.x); fma2(acc[3][3], a23.y, b23.y);
        }
        __syncthreads();
    }

    float bv[8];
#pragma unroll
    for (int j = 0; j < 8; j++) bv[j] = bias[h0 + tn * 8 + j];
#pragma unroll
    for (int i = 0; i < 4; i++) {
        int r  = r0 + tm * 4 + i;
        int bb = r >> 9;
        int tt = r & 511;
        float* orow = g_xproj + (((size_t)g * T_ + tt) * B_ + bb) * H_ + h0 + tn * 8;
#pragma unroll
        for (int jp = 0; jp < 4; jp++) {
            float2 v = make_float2(lo32(acc[i][jp]) + bv[jp * 2],
                                   hi32(acc[i][jp]) + bv[jp * 2 + 1]);
            *(float2*)(orow + jp * 2) = v;
        }
    }
}

// ---------------------------------------------------------------------------
// persistent HMMA recurrence. 128 CTAs x 128 thr (warp = gate).
// CTA tile: M=64 (4g x 16h) x N=32 batch x K=512.
//   A = R hi/lo f16, smem-resident 128KB, XOR-swizzled rows of 1024B
//   B = h f16 [32 n][512 k], staged per step (32KB), same swizzle
//   GEMM: ldmatrix (non-trans) + mma.sync m16n8k16 f16->f32
// smem: [0,128K) A | [128K,160K) B | [160K,+8448) act
// ---------------------------------------------------------------------------
__global__ __launch_bounds__(128, 1) void lstm_recur(
    const float* __restrict__ Rz, const float* __restrict__ Rs_,
    const float* __restrict__ Rf, const float* __restrict__ Ro,
    float* __restrict__ out)
{
    extern __shared__ char sm[];
    char*  smA  = sm;                       // 131072 B
    char*  smB  = sm + 131072;              // 32768 B
    float* actp = (float*)(sm + 163840);    // [64][33] floats
    const uint32_t smem_base = (uint32_t)__cvta_generic_to_shared(sm);
    const uint32_t SM_A = smem_base;
    const uint32_t SM_B = smem_base + 131072;

    const int tid = threadIdx.x;
    const int w   = tid >> 5;          // warp = gate
    const int l   = tid & 31;
    const int mt  = blockIdx.x >> 2;   // 32 h-tiles
    const int nt  = blockIdx.x & 3;    // 4 b-tiles
    const int h0  = mt * 16;
    const int b0  = nt * 32;

    // barrier sense (self-relative, persists across graph replays)
    unsigned s0 = 0;
    if (tid == 0) s0 = *(volatile unsigned*)&g_sns[nt][0];

    // ---- setup: A rows 0..63 = hi(f16 R), rows 64..127 = lo(f16 residual) ----
    {
        const int m  = tid & 63;            // row = gate*16 + hr
        const int kh = (tid >> 6) * 256;    // k half
        const int gg = m >> 4, hr = m & 15;
        const float* Rp = ((gg == 0) ? Rz : (gg == 1) ? Rs_ : (gg == 2) ? Rf : Ro)
                        + (size_t)(h0 + hr) * H_ + kh;
        char* rowHi = smA + m * 1024;
        char* rowLo = smA + (64 + m) * 1024;
        const int sx = m & 7;
#pragma unroll 8
        for (int k = 0; k < 256; k += 2) {
            float2 v = *(const float2*)(Rp + k);
            __half hv0 = __float2half(v.x);
            __half hv1 = __float2half(v.y);
            float r0 = v.x - __half2float(hv0);
            float r1 = v.y - __half2float(hv1);
            uint32_t hi = (uint32_t)__half_as_ushort(hv0)
                        | ((uint32_t)__half_as_ushort(hv1) << 16);
            uint32_t lo = (uint32_t)__half_as_ushort(__float2half(r0))
                        | ((uint32_t)__half_as_ushort(__float2half(r1)) << 16);
            int byte  = (kh + k) * 2;
            int chunk = byte >> 4;
            int off   = ((chunk ^ sx) << 4) + (byte & 15);
            *(uint32_t*)(rowHi + off) = hi;
            *(uint32_t*)(rowLo + off) = lo;
        }
    }
    __syncthreads();

    // ldmatrix lane-invariant addressing
    const uint32_t aRow  = (uint32_t)(w * 16 + (l & 15));
    const uint32_t aBase = SM_A + aRow * 1024u;
    const uint32_t aXor  = aRow & 7;
    const uint32_t aKl   = (uint32_t)(l >> 4);        // 0/1 (k octet)
    const uint32_t bRowL = (uint32_t)(l & 7);
    const uint32_t bKl   = (uint32_t)((l >> 3) & 1);
    const uint32_t bBase = SM_B + bRowL * 1024u;

    // epilogue identity (per mma accumulator layout)
    const int erow = l >> 2;            // m rows erow, erow+8
    const int ecol = (l & 3) * 2;

    // combine identity: 4 cells (b = tid&31, h = h0 + hgrp*4 .. +3)
    const int hgrp = tid >> 5;
    const int cbn  = tid & 31;
    float creg[4] = {0, 0, 0, 0}, hsum[4] = {0, 0, 0, 0};

    // B staging role
    const int srow = tid >> 2;          // 0..31
    const int sc0  = (tid & 3) * 16;    // 16 chunks of 16B
    const int sx2  = srow & 7;

    for (int t = 0; t < T_; t++) {
        // prefetch xproj for this thread's 16 accumulator cells
        float xv[4][4];
        {
            const float* xb = g_xproj + (((size_t)w * T_ + t) * B_ + b0) * H_ + h0;
#pragma unroll
            for (int nt4 = 0; nt4 < 4; nt4++) {
                int n0c = nt4 * 8 + ecol;
                xv[nt4][0] = xb[(size_t)(n0c)     * H_ + erow];
                xv[nt4][1] = xb[(size_t)(n0c + 1) * H_ + erow];
                xv[nt4][2] = xb[(size_t)(n0c)     * H_ + erow + 8];
                xv[nt4][3] = xb[(size_t)(n0c + 1) * H_ + erow + 8];
            }
        }

        float cacc[4][4];
#pragma unroll
        for (int i = 0; i < 4; i++)
#pragma unroll
            for (int j = 0; j < 4; j++) cacc[i][j] = 0.0f;

        if (t > 0) {
            // ---- stage B: g_hH[t&1][b0+row][k] -> swizzled smem ----
            {
                const char* gsrc = (const char*)&g_hH[t & 1][b0 + srow][0];
                char* sdst = smB + srow * 1024;
#pragma unroll
                for (int i = 0; i < 16; i++) {
                    int c = sc0 + i;
                    uint4 v = *(const uint4*)(gsrc + c * 16);
                    *(uint4*)(sdst + ((c ^ sx2) << 4)) = v;
                }
            }
            __syncthreads();

            // ---- GEMM: D[16 m][32 n] += (A_hi + A_lo) . B^T ----
#pragma unroll 4
            for (int ks = 0; ks < 32; ks++) {
                uint32_t aOff = ((((uint32_t)(ks * 2) + aKl) ^ aXor) << 4);
                uint32_t ah0, ah1, ah2, ah3, al0, al1, al2, al3;
                ldsm4(ah0, ah1, ah2, ah3, aBase + aOff);
                ldsm4(al0, al1, al2, al3, aBase + 65536u + aOff);
                uint32_t bOff = ((((uint32_t)(ks * 2) + bKl) ^ bRowL) << 4);
                uint32_t bf0[4], bf1[4];
#pragma unroll
                for (int nt4 = 0; nt4 < 4; nt4++)
                    ldsm2(bf0[nt4], bf1[nt4], bBase + nt4 * 8192u + bOff);
#pragma unroll
                for (int nt4 = 0; nt4 < 4; nt4++) {
                    mma16816(cacc[nt4], ah0, ah1, ah2, ah3, bf0[nt4], bf1[nt4]);
                    mma16816(cacc[nt4], al0, al1, al2, al3, bf0[nt4], bf1[nt4]);
                }
            }
        }

        // ---- epilogue: 16 pre-acts -> rational tanh/sigmoid -> act smem ----
        {
            const bool  isz = (w == 0);
            const float s1  = isz ? 1.0f : 0.5f;
            const float scm = isz ? 1.0f : 0.5f;
            const float sca = isz ? 0.0f : 0.5f;
#pragma unroll
            for (int nt4 = 0; nt4 < 4; nt4++) {
                float pn[4], qn[4], av[4];
#pragma unroll
                for (int j = 0; j < 4; j++) {
                    float v = (cacc[nt4][j] + xv[nt4][j]) * s1;
                    tanh_pq(v, pn[j], qn[j]);
                }
                div4(pn, qn, av);
#pragma unroll
                for (int j = 0; j < 4; j++) av[j] = fmaf(av[j], scm, sca);
                // j=0:(erow,n) j=1:(erow,n+1) j=2:(erow+8,n) j=3:(erow+8,n+1)
                int n = nt4 * 8 + ecol;
                actp[((erow)     * 4 + w) * 33 + n]     = av[0];
                actp[((erow)     * 4 + w) * 33 + n + 1] = av[1];
                actp[((erow + 8) * 4 + w) * 33 + n]     = av[2];
                actp[((erow + 8) * 4 + w) * 33 + n + 1] = av[3];
            }
        }
        __syncthreads();

        // ---- combine: 4 cells; c,h update; store h f16; accumulate sum ----
        {
            float pn[4], qn[4], tv[4], ov[4];
#pragma unroll
            for (int j = 0; j < 4; j++) {
                int r4 = (hgrp * 4 + j) * 4;
                float z = actp[(r4 + 0) * 33 + cbn];
                float s = actp[(r4 + 1) * 33 + cbn];
                float f = actp[(r4 + 2) * 33 + cbn];
                ov[j]   = actp[(r4 + 3) * 33 + cbn];
                float c = fmaf(s, z, f * creg[j]);
                creg[j] = c;
                tanh_pq(c, pn[j], qn[j]);
            }
            div4(pn, qn, tv);
            if (t < T_ - 1) {
                ushort hs[4];
#pragma unroll
                for (int j = 0; j < 4; j++) {
                    float hn = ov[j] * tv[j];
                    hsum[j] += hn;
                    hs[j] = __half_as_ushort(__float2half(hn));
                }
                uint2 pkt;
                pkt.x = (uint32_t)hs[0] | ((uint32_t)hs[1] << 16);
                pkt.y = (uint32_t)hs[2] | ((uint32_t)hs[3] << 16);
                *(uint2*)&g_hH[(t + 1) & 1][b0 + cbn][h0 + hgrp * 4] = pkt;
            } else {
                float4 r;
                r.x = (hsum[0] + ov[0] * tv[0]) * (1.0f / T_);
                r.y = (hsum[1] + ov[1] * tv[1]) * (1.0f / T_);
                r.z = (hsum[2] + ov[2] * tv[2]) * (1.0f / T_);
                r.w = (hsum[3] + ov[3] * tv[3]) * (1.0f / T_);
                *(float4*)(out + (size_t)(b0 + cbn) * H_ + h0 + hgrp * 4) = r;
            }
        }

        if (t < T_ - 1) {
            __syncthreads();               // act reuse + h stores done
            if (tid == 0) {
                unsigned target = s0 + (unsigned)(t + 1);
                __threadfence();
                unsigned arr = atomicAdd(&g_cnt[nt][0], 1u);
                if (arr == GRPSZ - 1) {
                    g_cnt[nt][0] = 0;
                    asm volatile("st.release.gpu.u32 [%0], %1;"
                                 :: "l"(&g_sns[nt][0]), "r"(target) : "memory");
                } else {
                    unsigned v;
                    do {
                        asm volatile("ld.acquire.gpu.u32 %0, [%1];"
                                     : "=r"(v) : "l"(&g_sns[nt][0]) : "memory");
                    } while ((int)(v - target) < 0);
                }
            }
            __syncthreads();
        }
    }
}

// ---------------------------------------------------------------------------
extern "C" void kernel_launch(void* const* d_in, const int* in_sizes, int n_in,
                              void* d_out, int out_size) {
    const float* x  = (const float*)d_in[0];
    const float* Wz = (const float*)d_in[1];
    const float* Ws = (const float*)d_in[2];
    const float* Wf = (const float*)d_in[3];
    const float* Wo = (const float*)d_in[4];
    const float* Rz = (const float*)d_in[5];
    const float* Rs = (const float*)d_in[6];
    const float* Rf = (const float*)d_in[7];
    const float* Ro = (const float*)d_in[8];
    const float* bz = (const float*)d_in[9];
    const float* bs = (const float*)d_in[10];
    const float* bf = (const float*)d_in[11];
    const float* bo = (const float*)d_in[12];

    const int smem_bytes = 131072 + 32768 + 64 * 33 * 4;   // ~168.5KB
    cudaFuncSetAttribute(lstm_recur,
                         cudaFuncAttributeMaxDynamicSharedMemorySize, smem_bytes);

    lstm_proj<<<dim3((B_ * T_) / 64, (4 * H_) / 64), 128>>>(
        x, Wz, Ws, Wf, Wo, bz, bs, bf, bo);
    lstm_recur<<<RCTAS, 128, smem_bytes>>>(Rz, Rs, Rf, Ro, (float*)d_out);
}